// round 2
// baseline (speedup 1.0000x reference)
#include <cuda_runtime.h>
#include <cuda_bf16.h>
#include <cstring>

// Problem constants
#define BB   8
#define CC   1024
#define HH   64
#define WW   64
#define NHD  16
#define HD   64
#define HWP  4096            // H*W
#define CHW  (CC * HWP)
#define EPSB 1e-3f

// ---------------------------------------------------------------------------
// Scratch buffers (device globals; no allocation allowed)
// ---------------------------------------------------------------------------
__device__ float g_y1[BB * CHW];   // after conv1+BN+SiLU
__device__ float g_y2[BB * CHW];   // after attention
__device__ float g_y3[BB * CHW];   // after depthwise+BN+SiLU

// ---------------------------------------------------------------------------
// Packed f32x2 helpers (FFMA2 — full-rate fp32 on sm_103a, PTX-only)
// ---------------------------------------------------------------------------
__device__ __forceinline__ unsigned long long pack2(float x) {
    unsigned long long r;
    unsigned int xi = __float_as_uint(x);
    asm("mov.b64 %0, {%1, %1};" : "=l"(r) : "r"(xi));
    return r;
}
__device__ __forceinline__ void fma2(unsigned long long& d,
                                     unsigned long long a,
                                     unsigned long long b) {
    asm("fma.rn.f32x2 %0, %1, %2, %3;" : "=l"(d) : "l"(a), "l"(b), "l"(d));
}
__device__ __forceinline__ void unpack2(unsigned long long u, float& lo, float& hi) {
    asm("mov.b64 {%0, %1}, %2;" : "=f"(lo), "=f"(hi) : "l"(u));
}

union F4U2 { float4 f; unsigned long long u[2]; };

// ---------------------------------------------------------------------------
// K1/K4: 1x1 conv as per-batch GEMM  Y[co,p] = sum_ci W[co,ci] * X[ci,p]
// fused BN + SiLU (+ optional residual). BM=BN=128, BK=16, 256 thr, 8x8/thr.
// ---------------------------------------------------------------------------
#define GBM 128
#define GBN 128
#define GBK 16

__global__ __launch_bounds__(256)
void conv1x1_bn_silu_kernel(const float* __restrict__ X,
                            const float* __restrict__ Wt,
                            const float* __restrict__ gam,
                            const float* __restrict__ bet,
                            const float* __restrict__ mu,
                            const float* __restrict__ var,
                            const float* __restrict__ res,   // may be null
                            float* __restrict__ out)
{
    const int n0 = blockIdx.x * GBN;
    const int m0 = blockIdx.y * GBM;
    const int bz = blockIdx.z;
    const float* Xb = X + (size_t)bz * CHW;

    __shared__ float As[GBK][GBM + 4];
    __shared__ float Bs[GBK][GBN + 4];

    const int tid  = threadIdx.x;
    const int aRow = tid >> 2;           // 0..63
    const int aCol = (tid & 3) * 4;      // 0,4,8,12
    const int bRow = tid >> 5;           // 0..7
    const int bCol = (tid & 31) * 4;     // 0..124
    const int tx = tid & 15;             // n
    const int ty = tid >> 4;             // m

    unsigned long long acc[8][4];
#pragma unroll
    for (int i = 0; i < 8; i++)
#pragma unroll
        for (int j = 0; j < 4; j++) acc[i][j] = 0ull;

    for (int kt = 0; kt < CC; kt += GBK) {
        // A tile: 128 rows (co) x 16 cols (ci), stored transposed
#pragma unroll
        for (int r = 0; r < 2; r++) {
            int row = aRow + r * 64;
            float4 va = *(const float4*)&Wt[(size_t)(m0 + row) * CC + kt + aCol];
            As[aCol + 0][row] = va.x;
            As[aCol + 1][row] = va.y;
            As[aCol + 2][row] = va.z;
            As[aCol + 3][row] = va.w;
        }
        // B tile: 16 rows (ci) x 128 cols (p)
#pragma unroll
        for (int r = 0; r < 2; r++) {
            int row = bRow + r * 8;
            float4 vb = *(const float4*)&Xb[(size_t)(kt + row) * HWP + n0 + bCol];
            *(float4*)&Bs[row][bCol] = vb;
        }
        __syncthreads();

#pragma unroll
        for (int k = 0; k < GBK; k++) {
            float4 a0 = *(const float4*)&As[k][ty * 8];
            float4 a1 = *(const float4*)&As[k][ty * 8 + 4];
            F4U2 bq0, bq1;
            bq0.f = *(const float4*)&Bs[k][tx * 8];
            bq1.f = *(const float4*)&Bs[k][tx * 8 + 4];
            unsigned long long b0 = bq0.u[0], b1 = bq0.u[1];
            unsigned long long b2 = bq1.u[0], b3 = bq1.u[1];
            float av[8] = {a0.x, a0.y, a0.z, a0.w, a1.x, a1.y, a1.z, a1.w};
#pragma unroll
            for (int i = 0; i < 8; i++) {
                unsigned long long a2 = pack2(av[i]);
                fma2(acc[i][0], a2, b0);
                fma2(acc[i][1], a2, b1);
                fma2(acc[i][2], a2, b2);
                fma2(acc[i][3], a2, b3);
            }
        }
        __syncthreads();
    }

    // epilogue: BN + SiLU (+ residual)
    float* outb = out + (size_t)bz * CHW;
    const float* resb = res ? res + (size_t)bz * CHW : nullptr;
#pragma unroll
    for (int i = 0; i < 8; i++) {
        const int co = m0 + ty * 8 + i;
        const float sc = gam[co] * rsqrtf(var[co] + EPSB);
        const float bi = bet[co] - mu[co] * sc;
        float vals[8];
#pragma unroll
        for (int j = 0; j < 4; j++) {
            float lo, hi;
            unpack2(acc[i][j], lo, hi);
            vals[2 * j] = lo;
            vals[2 * j + 1] = hi;
        }
        const size_t base = (size_t)co * HWP + n0 + tx * 8;
#pragma unroll
        for (int j = 0; j < 8; j++) {
            float y = vals[j] * sc + bi;
            y = y * (1.f / (1.f + __expf(-y)));           // SiLU
            if (resb) y += resb[base + j];
            vals[j] = y;
        }
        *(float4*)&outb[base]     = make_float4(vals[0], vals[1], vals[2], vals[3]);
        *(float4*)&outb[base + 4] = make_float4(vals[4], vals[5], vals[6], vals[7]);
    }
}

// ---------------------------------------------------------------------------
// K2: per-(b,nh,h) softmax-attention.
//   A[w][k]  = y1[b, nh*64+k, h, w]
//   P        = softmax over k (rows of A)
//   att[w,v] = sum_k P[w,k] * A[v,k]
//   y2[b, nh*64+v, h, w] = att[w,v]
// ---------------------------------------------------------------------------
__global__ __launch_bounds__(256)
void attn_kernel(const float* __restrict__ Y1, float* __restrict__ Y2)
{
    const int bid = blockIdx.x;
    const int h  = bid & 63;
    const int nh = (bid >> 6) & 15;
    const int b  = bid >> 10;

    const float* basep = Y1 + (size_t)b * CHW + (size_t)(nh * HD) * HWP + h * WW;

    __shared__ float A[64][65];
    __shared__ float P[64][65];

    const int tid = threadIdx.x;
#pragma unroll
    for (int it = 0; it < 16; it++) {
        int idx = it * 256 + tid;
        int k = idx >> 6, w = idx & 63;
        A[w][k] = basep[(size_t)k * HWP + w];
    }
    __syncthreads();

    const int lane = tid & 31, warp = tid >> 5;
#pragma unroll
    for (int r = 0; r < 8; r++) {
        int row = warp * 8 + r;
        float x0 = A[row][lane], x1 = A[row][lane + 32];
        float mx = fmaxf(x0, x1);
#pragma unroll
        for (int o = 16; o > 0; o >>= 1) mx = fmaxf(mx, __shfl_xor_sync(0xffffffffu, mx, o));
        float e0 = __expf(x0 - mx), e1 = __expf(x1 - mx);
        float s = e0 + e1;
#pragma unroll
        for (int o = 16; o > 0; o >>= 1) s += __shfl_xor_sync(0xffffffffu, s, o);
        float inv = 1.f / s;
        P[row][lane]      = e0 * inv;
        P[row][lane + 32] = e1 * inv;
    }
    __syncthreads();

    // 64x64x64 matmul: 4x4 per thread
    const int tx = tid & 15;   // v group
    const int ty = tid >> 4;   // w group
    float accv[4][4] = {};
#pragma unroll 4
    for (int k = 0; k < 64; k++) {
        float pv[4], av[4];
#pragma unroll
        for (int i = 0; i < 4; i++) {
            pv[i] = P[ty * 4 + i][k];
            av[i] = A[tx * 4 + i][k];
        }
#pragma unroll
        for (int i = 0; i < 4; i++)
#pragma unroll
            for (int j = 0; j < 4; j++)
                accv[i][j] = fmaf(pv[i], av[j], accv[i][j]);
    }
    __syncthreads();

    // stash att transposed (Att[v][w]) into A's storage, then coalesced store
#pragma unroll
    for (int i = 0; i < 4; i++)
#pragma unroll
        for (int j = 0; j < 4; j++)
            A[tx * 4 + j][ty * 4 + i] = accv[i][j];
    __syncthreads();

    float* outb = Y2 + (size_t)b * CHW + (size_t)(nh * HD) * HWP + h * WW;
#pragma unroll
    for (int it = 0; it < 16; it++) {
        int idx = it * 256 + tid;
        int v = idx >> 6, w = idx & 63;
        outb[(size_t)v * HWP + w] = A[v][w];
    }
}

// ---------------------------------------------------------------------------
// K3: depthwise 3x3 (SAME, zero pad) + BN + SiLU. One CTA per (b,c) plane.
// ---------------------------------------------------------------------------
__global__ __launch_bounds__(256)
void dwconv_bn_silu_kernel(const float* __restrict__ X,
                           const float* __restrict__ W2,
                           const float* __restrict__ gam,
                           const float* __restrict__ bet,
                           const float* __restrict__ mu,
                           const float* __restrict__ var,
                           float* __restrict__ out)
{
    const int bid = blockIdx.x;          // b*C + c
    const int c = bid & (CC - 1);
    const float* plane = X + (size_t)bid * HWP;

    __shared__ float T[66][66];
    const int tid = threadIdx.x;

    float wreg[9];
#pragma unroll
    for (int i = 0; i < 9; i++) wreg[i] = W2[c * 9 + i];
    const float sc = gam[c] * rsqrtf(var[c] + EPSB);
    const float bi = bet[c] - mu[c] * sc;

    for (int i = tid; i < 66 * 66; i += 256) {
        int r = i / 66, cc2 = i % 66;
        int y = r - 1, x = cc2 - 1;
        T[r][cc2] = (y >= 0 && y < 64 && x >= 0 && x < 64) ? plane[y * 64 + x] : 0.f;
    }
    __syncthreads();

    float* outp = out + (size_t)bid * HWP;
    for (int i = tid; i < HWP; i += 256) {
        int y = i >> 6, x = i & 63;
        float s = 0.f;
#pragma unroll
        for (int dy = 0; dy < 3; dy++)
#pragma unroll
            for (int dx = 0; dx < 3; dx++)
                s = fmaf(wreg[dy * 3 + dx], T[y + dy][x + dx], s);
        s = s * sc + bi;
        s = s * (1.f / (1.f + __expf(-s)));
        outp[i] = s;
    }
}

// ---------------------------------------------------------------------------
// Launch. Input binding follows setup_inputs() dict order:
//   0:x  1:w1  2:w2  3:w3  4:g1 5:b1 6:m1 7:v1  8:g2 9:b2 10:m2 11:v2
//   12:g3 13:b3 14:m3 15:v3
// Verified against in_sizes signature (w1/w3: 1048576, w2: 9216, BN: 1024).
// ---------------------------------------------------------------------------
extern "C" void kernel_launch(void* const* d_in, const int* in_sizes, int n_in,
                              void* d_out, int out_size)
{
    const float* x  = (const float*)d_in[0];
    const float* w1 = (const float*)d_in[1];
    const float* w2 = (const float*)d_in[2];
    const float* w3 = (const float*)d_in[3];
    const float* g1 = (const float*)d_in[4];
    const float* b1 = (const float*)d_in[5];
    const float* m1 = (const float*)d_in[6];
    const float* v1 = (const float*)d_in[7];
    const float* g2 = (const float*)d_in[8];
    const float* b2 = (const float*)d_in[9];
    const float* m2 = (const float*)d_in[10];
    const float* v2 = (const float*)d_in[11];
    const float* g3 = (const float*)d_in[12];
    const float* b3 = (const float*)d_in[13];
    const float* m3 = (const float*)d_in[14];
    const float* v3 = (const float*)d_in[15];
    float* out = (float*)d_out;

    // Defensive: if the layout ever differs, fall back to signature matching.
    if (!(in_sizes[1] == CC * CC && in_sizes[2] == CC * 9 && in_sizes[3] == CC * CC)) {
        // locate by sizes (order-preserving within each class)
        const float* big[2] = {nullptr, nullptr}; int nbig = 0;
        const float* small9216 = nullptr;
        const float* perch[12]; int nper = 0;
        for (int i = 1; i < n_in; i++) {
            if (in_sizes[i] == CC * CC && nbig < 2) big[nbig++] = (const float*)d_in[i];
            else if (in_sizes[i] == CC * 9) small9216 = (const float*)d_in[i];
            else if (in_sizes[i] == CC && nper < 12) perch[nper++] = (const float*)d_in[i];
        }
        w1 = big[0]; w3 = big[1]; w2 = small9216;
        g1 = perch[0]; b1 = perch[1]; m1 = perch[2];  v1 = perch[3];
        g2 = perch[4]; b2 = perch[5]; m2 = perch[6];  v2 = perch[7];
        g3 = perch[8]; b3 = perch[9]; m3 = perch[10]; v3 = perch[11];
    }

    float *p_y1, *p_y2, *p_y3;
    cudaGetSymbolAddress((void**)&p_y1, g_y1);
    cudaGetSymbolAddress((void**)&p_y2, g_y2);
    cudaGetSymbolAddress((void**)&p_y3, g_y3);

    dim3 gemm_grid(HWP / GBN, CC / GBM, BB);   // (32, 8, 8)

    conv1x1_bn_silu_kernel<<<gemm_grid, 256>>>(x, w1, g1, b1, m1, v1, nullptr, p_y1);
    attn_kernel<<<BB * NHD * HH, 256>>>(p_y1, p_y2);
    dwconv_bn_silu_kernel<<<BB * CC, 256>>>(p_y2, w2, g2, b2, m2, v2, p_y3);
    conv1x1_bn_silu_kernel<<<gemm_grid, 256>>>(p_y3, w3, g3, b3, m3, v3, x, out);
}

// round 4
// speedup vs baseline: 1.5678x; 1.5678x over previous
#include <cuda_runtime.h>
#include <cuda_bf16.h>
#include <cstdint>

// Problem constants
#define BB   8
#define CC   1024
#define HH   64
#define WW   64
#define NHD  16
#define HD   64
#define HWP  4096
#define CHW  (CC * HWP)
#define EPSB 1e-3f

// GEMM tiling (warp-level mma.sync path; tcgen05 is unavailable on this
// build's PTX target compute_103)
#define BM   128
#define BN   128
#define BKE  32              // bf16 K elems per stage
#define LDT  40              // padded SMEM row length (elems) -> 80B, conflict-free
#define NPASS 3
#define NKT  (CC / BKE)      // 32
#define NIT  (NPASS * NKT)   // 96

// ---------------------------------------------------------------------------
// Scratch (device globals; no allocation allowed)
// ---------------------------------------------------------------------------
__device__ float g_y1[BB * CHW];
__device__ float g_y2[BB * CHW];
__device__ float g_y3[BB * CHW];
__device__ __nv_bfloat16 g_w1hi[CC * CC], g_w1lo[CC * CC];
__device__ __nv_bfloat16 g_w3hi[CC * CC], g_w3lo[CC * CC];
__device__ __nv_bfloat16 g_bhi[BB * HWP * CC];   // [b][p][ci]
__device__ __nv_bfloat16 g_blo[BB * HWP * CC];

// ---------------------------------------------------------------------------
// PTX helpers (all legal on compute_103: cp.async / ldmatrix / mma.sync)
// ---------------------------------------------------------------------------
__device__ __forceinline__ uint32_t smem_u32(const void* p) {
    uint32_t a;
    asm("{ .reg .u64 t; cvta.to.shared.u64 t, %1; cvt.u32.u64 %0, t; }" : "=r"(a) : "l"(p));
    return a;
}
__device__ __forceinline__ void cp_async16(uint32_t saddr, const void* gaddr) {
    asm volatile("cp.async.cg.shared.global [%0], [%1], 16;" :: "r"(saddr), "l"(gaddr));
}
__device__ __forceinline__ void cp_commit() {
    asm volatile("cp.async.commit_group;" ::: "memory");
}
template <int N>
__device__ __forceinline__ void cp_wait() {
    asm volatile("cp.async.wait_group %0;" :: "n"(N) : "memory");
}
__device__ __forceinline__ void ldmx4(uint32_t* r, uint32_t addr) {
    asm volatile("ldmatrix.sync.aligned.m8n8.x4.shared.b16 {%0,%1,%2,%3}, [%4];"
                 : "=r"(r[0]), "=r"(r[1]), "=r"(r[2]), "=r"(r[3]) : "r"(addr));
}
__device__ __forceinline__ void mma16816(float* c, const uint32_t* a,
                                         uint32_t b0, uint32_t b1) {
    asm volatile(
        "mma.sync.aligned.m16n8k16.row.col.f32.bf16.bf16.f32 "
        "{%0,%1,%2,%3}, {%4,%5,%6,%7}, {%8,%9}, {%0,%1,%2,%3};"
        : "+f"(c[0]), "+f"(c[1]), "+f"(c[2]), "+f"(c[3])
        : "r"(a[0]), "r"(a[1]), "r"(a[2]), "r"(a[3]), "r"(b0), "r"(b1));
}

// ---------------------------------------------------------------------------
// Split-fp32 helpers
// ---------------------------------------------------------------------------
__device__ __forceinline__ void split_bf16(float v, __nv_bfloat16& hi, __nv_bfloat16& lo) {
    hi = __float2bfloat16(v);
    lo = __float2bfloat16(v - __bfloat162float(hi));
}

__global__ void convert_w_kernel(const float* __restrict__ W,
                                 __nv_bfloat16* __restrict__ Whi,
                                 __nv_bfloat16* __restrict__ Wlo)
{
    int i = blockIdx.x * blockDim.x + threadIdx.x;
    if (i < CC * CC) split_bf16(W[i], Whi[i], Wlo[i]);
}

// Transpose+convert: X fp32 [b][ci][p] -> hi/lo bf16 [b][p][ci]
__global__ __launch_bounds__(256)
void transpose_cvt_kernel(const float* __restrict__ X,
                          __nv_bfloat16* __restrict__ Thi,
                          __nv_bfloat16* __restrict__ Tlo)
{
    __shared__ float t[32][33];
    const int p0 = blockIdx.x * 32;
    const int c0 = blockIdx.y * 32;
    const int b  = blockIdx.z;
    const int tx = threadIdx.x & 31, ty = threadIdx.x >> 5;

    const float* Xb = X + (size_t)b * CHW;
#pragma unroll
    for (int i = 0; i < 4; i++)
        t[ty + 8 * i][tx] = Xb[(size_t)(c0 + ty + 8 * i) * HWP + p0 + tx];
    __syncthreads();

    __nv_bfloat16* Th = Thi + (size_t)b * HWP * CC;
    __nv_bfloat16* Tl = Tlo + (size_t)b * HWP * CC;
#pragma unroll
    for (int i = 0; i < 4; i++) {
        float v = t[tx][ty + 8 * i];
        __nv_bfloat16 hi, lo;
        split_bf16(v, hi, lo);
        size_t o = (size_t)(p0 + ty + 8 * i) * CC + c0 + tx;
        Th[o] = hi;
        Tl[o] = lo;
    }
}

// ---------------------------------------------------------------------------
// Warp-MMA split-bf16 GEMM + BN + SiLU (+residual)
//   out[co][p] = silu(BN(sum_ci W[co][ci] * XT[p][ci])) (+ res)
// ---------------------------------------------------------------------------
__global__ __launch_bounds__(256)
void gemm_mma_kernel(const __nv_bfloat16* __restrict__ Ahi,
                     const __nv_bfloat16* __restrict__ Alo,
                     const __nv_bfloat16* __restrict__ Bhi_,
                     const __nv_bfloat16* __restrict__ Blo_,
                     const float* __restrict__ gam,
                     const float* __restrict__ bet,
                     const float* __restrict__ mu,
                     const float* __restrict__ var,
                     const float* __restrict__ res,
                     float* __restrict__ out)
{
    __shared__ __nv_bfloat16 sA[2][BM * LDT];
    __shared__ __nv_bfloat16 sB[2][BN * LDT];

    const int tid  = threadIdx.x;
    const int warp = tid >> 5, lane = tid & 31;
    const int warp_m = warp >> 2;          // 0..1 -> 64 rows each
    const int warp_n = warp & 3;           // 0..3 -> 32 cols each

    const int n0 = blockIdx.x * BN;
    const int m0 = blockIdx.y * BM;
    const int bz = blockIdx.z;
    const __nv_bfloat16* Bhi = Bhi_ + (size_t)bz * HWP * CC;
    const __nv_bfloat16* Blo = Blo_ + (size_t)bz * HWP * CC;

    float acc[4][4][4];
#pragma unroll
    for (int i = 0; i < 4; i++)
#pragma unroll
        for (int j = 0; j < 4; j++)
#pragma unroll
            for (int q = 0; q < 4; q++) acc[i][j][q] = 0.f;

    // staging coords: 1024 16B-chunks (512 A + 512 B), 4 per thread
    const int rcA0 = tid;                 // j=0,1 -> A ; j=2,3 -> B
    // per-chunk: row = rc>>2, kc = (rc&3)*8

    auto stage = [&](int it, int s) {
        const int pass = it >> 5;
        const int kt = (it & (NKT - 1)) * BKE;
        const __nv_bfloat16* Ap = (pass == 2) ? Alo : Ahi;
        const __nv_bfloat16* Bp = (pass == 1) ? Blo : Bhi;
        const uint32_t sa = smem_u32(sA[s]);
        const uint32_t sbb = smem_u32(sB[s]);
#pragma unroll
        for (int j = 0; j < 2; j++) {
            int rc = rcA0 + j * 256;
            int row = rc >> 2, kc = (rc & 3) * 8;
            cp_async16(sa + (row * LDT + kc) * 2,
                       Ap + (size_t)(m0 + row) * CC + kt + kc);
        }
#pragma unroll
        for (int j = 0; j < 2; j++) {
            int rc = rcA0 + j * 256;
            int row = rc >> 2, kc = (rc & 3) * 8;
            cp_async16(sbb + (row * LDT + kc) * 2,
                       Bp + (size_t)(n0 + row) * CC + kt + kc);
        }
        cp_commit();
    };

    const int lr = lane & 15;
    const int lh = (lane >> 4) * 8;       // k offset for upper 16 lanes

    stage(0, 0);
    int buf = 0;

    for (int it = 0; it < NIT; it++) {
        if (it + 1 < NIT) {
            stage(it + 1, buf ^ 1);
            cp_wait<1>();
        } else {
            cp_wait<0>();
        }
        __syncthreads();

        const uint32_t sa = smem_u32(sA[buf]);
        const uint32_t sbb = smem_u32(sB[buf]);
#pragma unroll
        for (int kh = 0; kh < 2; kh++) {
            const int k16 = kh * 16;
            uint32_t af[4][4];
#pragma unroll
            for (int mt = 0; mt < 4; mt++)
                ldmx4(af[mt], sa + ((warp_m * 64 + mt * 16 + lr) * LDT + k16 + lh) * 2);
            uint32_t bfr[2][4];
#pragma unroll
            for (int nt2 = 0; nt2 < 2; nt2++)
                ldmx4(bfr[nt2], sbb + ((warp_n * 32 + nt2 * 16 + lr) * LDT + k16 + lh) * 2);
#pragma unroll
            for (int mt = 0; mt < 4; mt++)
#pragma unroll
                for (int nt = 0; nt < 4; nt++) {
                    uint32_t b0 = bfr[nt >> 1][nt & 1];
                    uint32_t b1 = bfr[nt >> 1][(nt & 1) + 2];
                    mma16816(acc[mt][nt], af[mt], b0, b1);
                }
        }
        __syncthreads();
        buf ^= 1;
    }

    // epilogue: BN + SiLU (+res). Thread holds rows m, m+8 per m-tile,
    // cols n..n+1 per n-tile at n = nt*8 + (lane%4)*2.
    const int qrow = lane >> 2;            // 0..7
    const int qcol = (lane & 3) * 2;
#pragma unroll
    for (int mt = 0; mt < 4; mt++) {
#pragma unroll
        for (int half = 0; half < 2; half++) {
            const int co = m0 + warp_m * 64 + mt * 16 + qrow + half * 8;
            const float sc = gam[co] * rsqrtf(var[co] + EPSB);
            const float bi = bet[co] - mu[co] * sc;
            float* orow = out + (size_t)bz * CHW + (size_t)co * HWP + n0 + warp_n * 32;
            const float* rrow = res ? res + (size_t)bz * CHW + (size_t)co * HWP
                                        + n0 + warp_n * 32
                                    : nullptr;
#pragma unroll
            for (int nt = 0; nt < 4; nt++) {
                const int nn = nt * 8 + qcol;
                float y0 = acc[mt][nt][half * 2 + 0] * sc + bi;
                float y1 = acc[mt][nt][half * 2 + 1] * sc + bi;
                y0 = y0 * (1.f / (1.f + __expf(-y0)));
                y1 = y1 * (1.f / (1.f + __expf(-y1)));
                if (rrow) { y0 += rrow[nn]; y1 += rrow[nn + 1]; }
                float2 v = make_float2(y0, y1);
                *(float2*)&orow[nn] = v;
            }
        }
    }
}

// ---------------------------------------------------------------------------
// K2: per-(b,nh,h) softmax-attention (fp32)
// ---------------------------------------------------------------------------
__global__ __launch_bounds__(256)
void attn_kernel(const float* __restrict__ Y1, float* __restrict__ Y2)
{
    const int bid = blockIdx.x;
    const int h  = bid & 63;
    const int nh = (bid >> 6) & 15;
    const int b  = bid >> 10;

    const float* basep = Y1 + (size_t)b * CHW + (size_t)(nh * HD) * HWP + h * WW;

    __shared__ float A[64][65];
    __shared__ float P[64][65];

    const int tid = threadIdx.x;
#pragma unroll
    for (int it = 0; it < 16; it++) {
        int idx = it * 256 + tid;
        int k = idx >> 6, w = idx & 63;
        A[w][k] = basep[(size_t)k * HWP + w];
    }
    __syncthreads();

    const int lane = tid & 31, warp = tid >> 5;
#pragma unroll
    for (int r = 0; r < 8; r++) {
        int row = warp * 8 + r;
        float x0 = A[row][lane], x1 = A[row][lane + 32];
        float mx = fmaxf(x0, x1);
#pragma unroll
        for (int o = 16; o > 0; o >>= 1) mx = fmaxf(mx, __shfl_xor_sync(0xffffffffu, mx, o));
        float e0 = __expf(x0 - mx), e1 = __expf(x1 - mx);
        float s = e0 + e1;
#pragma unroll
        for (int o = 16; o > 0; o >>= 1) s += __shfl_xor_sync(0xffffffffu, s, o);
        float inv = 1.f / s;
        P[row][lane]      = e0 * inv;
        P[row][lane + 32] = e1 * inv;
    }
    __syncthreads();

    const int tx = tid & 15;
    const int ty = tid >> 4;
    float accv[4][4] = {};
#pragma unroll 4
    for (int k = 0; k < 64; k++) {
        float pv[4], av[4];
#pragma unroll
        for (int i = 0; i < 4; i++) {
            pv[i] = P[ty * 4 + i][k];
            av[i] = A[tx * 4 + i][k];
        }
#pragma unroll
        for (int i = 0; i < 4; i++)
#pragma unroll
            for (int j = 0; j < 4; j++)
                accv[i][j] = fmaf(pv[i], av[j], accv[i][j]);
    }
    __syncthreads();

#pragma unroll
    for (int i = 0; i < 4; i++)
#pragma unroll
        for (int j = 0; j < 4; j++)
            A[tx * 4 + j][ty * 4 + i] = accv[i][j];
    __syncthreads();

    float* outb = Y2 + (size_t)b * CHW + (size_t)(nh * HD) * HWP + h * WW;
#pragma unroll
    for (int it = 0; it < 16; it++) {
        int idx = it * 256 + tid;
        int v = idx >> 6, w = idx & 63;
        outb[(size_t)v * HWP + w] = A[v][w];
    }
}

// ---------------------------------------------------------------------------
// K3: depthwise 3x3 + BN + SiLU
// ---------------------------------------------------------------------------
__global__ __launch_bounds__(256)
void dwconv_bn_silu_kernel(const float* __restrict__ X,
                           const float* __restrict__ W2,
                           const float* __restrict__ gam,
                           const float* __restrict__ bet,
                           const float* __restrict__ mu,
                           const float* __restrict__ var,
                           float* __restrict__ out)
{
    const int bid = blockIdx.x;
    const int c = bid & (CC - 1);
    const float* plane = X + (size_t)bid * HWP;

    __shared__ float T[66][66];
    const int tid = threadIdx.x;

    float wreg[9];
#pragma unroll
    for (int i = 0; i < 9; i++) wreg[i] = W2[c * 9 + i];
    const float sc = gam[c] * rsqrtf(var[c] + EPSB);
    const float bi = bet[c] - mu[c] * sc;

    for (int i = tid; i < 66 * 66; i += 256) {
        int r = i / 66, cc2 = i % 66;
        int y = r - 1, x = cc2 - 1;
        T[r][cc2] = (y >= 0 && y < 64 && x >= 0 && x < 64) ? plane[y * 64 + x] : 0.f;
    }
    __syncthreads();

    float* outp = out + (size_t)bid * HWP;
    for (int i = tid; i < HWP; i += 256) {
        int y = i >> 6, x = i & 63;
        float s = 0.f;
#pragma unroll
        for (int dy = 0; dy < 3; dy++)
#pragma unroll
            for (int dx = 0; dx < 3; dx++)
                s = fmaf(wreg[dy * 3 + dx], T[y + dy][x + dx], s);
        s = s * sc + bi;
        s = s * (1.f / (1.f + __expf(-s)));
        outp[i] = s;
    }
}

// ---------------------------------------------------------------------------
// Launch. setup_inputs() dict order:
//   0:x 1:w1 2:w2 3:w3 4:g1 5:b1 6:m1 7:v1 8:g2 9:b2 10:m2 11:v2 12:g3 13:b3 14:m3 15:v3
// ---------------------------------------------------------------------------
extern "C" void kernel_launch(void* const* d_in, const int* in_sizes, int n_in,
                              void* d_out, int out_size)
{
    const float* x  = (const float*)d_in[0];
    const float* w1 = (const float*)d_in[1];
    const float* w2 = (const float*)d_in[2];
    const float* w3 = (const float*)d_in[3];
    const float* g1 = (const float*)d_in[4];
    const float* b1 = (const float*)d_in[5];
    const float* m1 = (const float*)d_in[6];
    const float* v1 = (const float*)d_in[7];
    const float* g2 = (const float*)d_in[8];
    const float* b2 = (const float*)d_in[9];
    const float* m2 = (const float*)d_in[10];
    const float* v2 = (const float*)d_in[11];
    const float* g3 = (const float*)d_in[12];
    const float* b3 = (const float*)d_in[13];
    const float* m3 = (const float*)d_in[14];
    const float* v3 = (const float*)d_in[15];
    float* out = (float*)d_out;

    if (!(in_sizes[1] == CC * CC && in_sizes[2] == CC * 9 && in_sizes[3] == CC * CC)) {
        const float* big[2] = {nullptr, nullptr}; int nbig = 0;
        const float* small9216 = nullptr;
        const float* perch[12]; int nper = 0;
        for (int i = 1; i < n_in; i++) {
            if (in_sizes[i] == CC * CC && nbig < 2) big[nbig++] = (const float*)d_in[i];
            else if (in_sizes[i] == CC * 9) small9216 = (const float*)d_in[i];
            else if (in_sizes[i] == CC && nper < 12) perch[nper++] = (const float*)d_in[i];
        }
        w1 = big[0]; w3 = big[1]; w2 = small9216;
        g1 = perch[0]; b1 = perch[1]; m1 = perch[2];  v1 = perch[3];
        g2 = perch[4]; b2 = perch[5]; m2 = perch[6];  v2 = perch[7];
        g3 = perch[8]; b3 = perch[9]; m3 = perch[10]; v3 = perch[11];
    }

    float *p_y1, *p_y2, *p_y3;
    __nv_bfloat16 *p_w1hi, *p_w1lo, *p_w3hi, *p_w3lo, *p_bhi, *p_blo;
    cudaGetSymbolAddress((void**)&p_y1, g_y1);
    cudaGetSymbolAddress((void**)&p_y2, g_y2);
    cudaGetSymbolAddress((void**)&p_y3, g_y3);
    cudaGetSymbolAddress((void**)&p_w1hi, g_w1hi);
    cudaGetSymbolAddress((void**)&p_w1lo, g_w1lo);
    cudaGetSymbolAddress((void**)&p_w3hi, g_w3hi);
    cudaGetSymbolAddress((void**)&p_w3lo, g_w3lo);
    cudaGetSymbolAddress((void**)&p_bhi, g_bhi);
    cudaGetSymbolAddress((void**)&p_blo, g_blo);

    dim3 tgrid(HWP / 32, CC / 32, BB);
    dim3 ggrid(HWP / BN, CC / BM, BB);     // (32, 8, 8)

    convert_w_kernel<<<(CC * CC + 511) / 512, 512>>>(w1, p_w1hi, p_w1lo);
    convert_w_kernel<<<(CC * CC + 511) / 512, 512>>>(w3, p_w3hi, p_w3lo);
    transpose_cvt_kernel<<<tgrid, 256>>>(x, p_bhi, p_blo);
    gemm_mma_kernel<<<ggrid, 256>>>(p_w1hi, p_w1lo, p_bhi, p_blo,
                                    g1, b1, m1, v1, nullptr, p_y1);
    attn_kernel<<<BB * NHD * HH, 256>>>(p_y1, p_y2);
    dwconv_bn_silu_kernel<<<BB * CC, 256>>>(p_y2, w2, g2, b2, m2, v2, p_y3);
    transpose_cvt_kernel<<<tgrid, 256>>>(p_y3, p_bhi, p_blo);
    gemm_mma_kernel<<<ggrid, 256>>>(p_w3hi, p_w3lo, p_bhi, p_blo,
                                    g3, b3, m3, v3, x, out);
}